// round 1
// baseline (speedup 1.0000x reference)
#include <cuda_runtime.h>
#include <cuda_bf16.h>
#include <cstdint>

// Problem constants
#define TT 2048
#define DD 2048
#define HH 16
#define CC 128
#define D3 6144

// ---------------------------------------------------------------------------
// Scratch (static device globals — no allocation allowed)
// ---------------------------------------------------------------------------
__device__ float g_qkv[(size_t)TT * D3];        // 50 MB
__device__ float g_q[(size_t)HH * TT * CC];     // 16 MB  [H][T][C]
__device__ float g_k[(size_t)HH * TT * CC];     // 16 MB
__device__ float g_v[(size_t)HH * TT * CC];     // 16 MB
__device__ float g_att[(size_t)TT * DD];        // 16 MB  [T][D]

// ---------------------------------------------------------------------------
// SGEMM (NT): C[M,N] = A[M,K] @ B[N,K]^T + bias[N]
// 128x128 block, BK=16, 8x8 per thread, 256 threads.
// ---------------------------------------------------------------------------
__global__ __launch_bounds__(256) void sgemm_nt_bias(
    const float* __restrict__ A, const float* __restrict__ B,
    const float* __restrict__ bias, float* __restrict__ C,
    int M, int N, int K)
{
    __shared__ float As[16][128];
    __shared__ float Bs[16][128];
    const int tid = threadIdx.x;
    const int m0 = blockIdx.y << 7;
    const int n0 = blockIdx.x << 7;
    const int tr = (tid >> 4) << 3;   // thread row base within block
    const int tc = (tid & 15) << 3;   // thread col base within block
    const int lr = tid >> 2;          // load row (0..63), +64 on second pass
    const int lk = (tid & 3) << 2;    // load k offset {0,4,8,12}

    float acc[8][8];
#pragma unroll
    for (int i = 0; i < 8; i++)
#pragma unroll
        for (int j = 0; j < 8; j++) acc[i][j] = 0.f;

    for (int k0 = 0; k0 < K; k0 += 16) {
#pragma unroll
        for (int i = 0; i < 2; i++) {
            int row = lr + i * 64;
            float4 a4 = *(const float4*)(A + (size_t)(m0 + row) * K + k0 + lk);
            As[lk + 0][row] = a4.x; As[lk + 1][row] = a4.y;
            As[lk + 2][row] = a4.z; As[lk + 3][row] = a4.w;
            float4 b4 = *(const float4*)(B + (size_t)(n0 + row) * K + k0 + lk);
            Bs[lk + 0][row] = b4.x; Bs[lk + 1][row] = b4.y;
            Bs[lk + 2][row] = b4.z; Bs[lk + 3][row] = b4.w;
        }
        __syncthreads();
#pragma unroll
        for (int kk = 0; kk < 16; kk++) {
            float ra[8], rb[8];
#pragma unroll
            for (int i = 0; i < 8; i++) ra[i] = As[kk][tr + i];
#pragma unroll
            for (int j = 0; j < 8; j++) rb[j] = Bs[kk][tc + j];
#pragma unroll
            for (int i = 0; i < 8; i++)
#pragma unroll
                for (int j = 0; j < 8; j++)
                    acc[i][j] = fmaf(ra[i], rb[j], acc[i][j]);
        }
        __syncthreads();
    }

#pragma unroll
    for (int i = 0; i < 8; i++) {
        float* crow = C + (size_t)(m0 + tr + i) * N + n0 + tc;
#pragma unroll
        for (int j = 0; j < 8; j++)
            crow[j] = acc[i][j] + bias[n0 + tc + j];
    }
}

// ---------------------------------------------------------------------------
// Per-(t,h): layernorm over C=128 for q and k, RoPE, split + relayout to
// [H][T][C]. v is just relayouted. 128 threads = one channel each.
// ---------------------------------------------------------------------------
__global__ __launch_bounds__(128) void ln_rope_split(
    const float* __restrict__ qkv,
    const float* __restrict__ qw, const float* __restrict__ kw,
    float* __restrict__ Qo, float* __restrict__ Ko, float* __restrict__ Vo)
{
    const int t = blockIdx.x, h = blockIdx.y, c = threadIdx.x;
    const float* row = qkv + (size_t)t * D3 + h * CC;
    float qv = row[c];
    float kv = row[DD + c];
    float vv = row[2 * DD + c];

    float s0 = qv, s1 = qv * qv, s2 = kv, s3 = kv * kv;
#pragma unroll
    for (int o = 16; o > 0; o >>= 1) {
        s0 += __shfl_xor_sync(0xffffffffu, s0, o);
        s1 += __shfl_xor_sync(0xffffffffu, s1, o);
        s2 += __shfl_xor_sync(0xffffffffu, s2, o);
        s3 += __shfl_xor_sync(0xffffffffu, s3, o);
    }
    __shared__ float red[4][4];
    __shared__ float sn[2][128];
    if ((c & 31) == 0) {
        int w = c >> 5;
        red[w][0] = s0; red[w][1] = s1; red[w][2] = s2; red[w][3] = s3;
    }
    __syncthreads();
    float qs  = red[0][0] + red[1][0] + red[2][0] + red[3][0];
    float qss = red[0][1] + red[1][1] + red[2][1] + red[3][1];
    float ks  = red[0][2] + red[1][2] + red[2][2] + red[3][2];
    float kss = red[0][3] + red[1][3] + red[2][3] + red[3][3];

    const float inv128 = 1.f / 128.f;
    float qmu = qs * inv128, kmu = ks * inv128;
    float qvar = qss * inv128 - qmu * qmu;
    float kvar = kss * inv128 - kmu * kmu;
    float qr = rsqrtf(qvar + 1e-6f);
    float kr = rsqrtf(kvar + 1e-6f);
    float qn = (qv - qmu) * qr * qw[c];
    float kn = (kv - kmu) * kr * kw[c];
    sn[0][c] = qn;
    sn[1][c] = kn;
    __syncthreads();

    // RoPE: pair i = c/2; y[2i] = x[2i]*cos - x[2i+1]*sin ; y[2i+1] = x[2i+1]*cos + x[2i]*sin
    int i = c >> 1;
    float inv = __powf(10000.f, -(float)(2 * i) * (1.f / 128.f));
    float fr = (float)t * inv;
    float sf, cf;
    sincosf(fr, &sf, &cf);   // accurate version (args up to ~2047 rad)
    float qp = sn[0][c ^ 1], kp = sn[1][c ^ 1];
    float qo = (c & 1) ? fmaf(qn, cf, qp * sf) : fmaf(qn, cf, -qp * sf);
    float ko = (c & 1) ? fmaf(kn, cf, kp * sf) : fmaf(kn, cf, -kp * sf);

    size_t oidx = ((size_t)h * TT + t) * CC + c;
    Qo[oidx] = qo;
    Ko[oidx] = ko;
    Vo[oidx] = vv;
}

// ---------------------------------------------------------------------------
// Causal flash attention, fp32. Per block: 64 query rows of one head.
// Online softmax over key blocks of 64. Output written to [T][D] layout.
// Dyn smem: Qt[128][64] + Kt[128][64] + Vs[64][128] + Ss[64][65] = 112.25 KB
// ---------------------------------------------------------------------------
#define FA_SMEM ((128 * 64 + 128 * 64 + 64 * 128 + 64 * 65) * 4)

__global__ __launch_bounds__(256) void flash_attn(
    const float* __restrict__ Qg, const float* __restrict__ Kg,
    const float* __restrict__ Vg, float* __restrict__ Og)
{
    extern __shared__ float sm[];
    float* Qt = sm;                 // [128][64] (transposed: [c][r])
    float* Kt = Qt + 128 * 64;      // [128][64]
    float* Vs = Kt + 128 * 64;      // [64][128]
    float* Ss = Vs + 64 * 128;      // [64][65] (padded)
    __shared__ float m_s[64], l_s[64], al_s[64];

    const int tid = threadIdx.x;
    const int qb = blockIdx.x, h = blockIdx.y;
    const int qm0 = qb * 64;
    const float* Qh = Qg + (size_t)h * TT * CC;
    const float* Kh = Kg + (size_t)h * TT * CC;
    const float* Vh = Vg + (size_t)h * TT * CC;
    const float scale = 0.08838834764831845f;   // 1/sqrt(128)

    // Load Q tile transposed, pre-scaled.
#pragma unroll
    for (int i = 0; i < 8; i++) {
        int id = tid + i * 256;
        int r = id >> 5, cc = (id & 31) << 2;
        float4 q4 = *(const float4*)(Qh + (size_t)(qm0 + r) * CC + cc);
        Qt[(cc + 0) * 64 + r] = q4.x * scale;
        Qt[(cc + 1) * 64 + r] = q4.y * scale;
        Qt[(cc + 2) * 64 + r] = q4.z * scale;
        Qt[(cc + 3) * 64 + r] = q4.w * scale;
    }
    if (tid < 64) { m_s[tid] = -1e30f; l_s[tid] = 0.f; }

    float o[4][8];
#pragma unroll
    for (int i = 0; i < 4; i++)
#pragma unroll
        for (int j = 0; j < 8; j++) o[i][j] = 0.f;

    const int rG  = (tid >> 4) << 2;   // 4 query rows: rG..rG+3
    const int cG4 = (tid & 15) << 2;   // 4 score cols
    const int cG8 = (tid & 15) << 3;   // 8 output cols

    for (int kb = 0; kb <= qb; kb++) {
        __syncthreads();   // protect Kt/Vs/Ss reuse (and Qt on first iter)
#pragma unroll
        for (int i = 0; i < 8; i++) {
            int id = tid + i * 256;
            int r = id >> 5, cc = (id & 31) << 2;
            float4 k4 = *(const float4*)(Kh + (size_t)(kb * 64 + r) * CC + cc);
            Kt[(cc + 0) * 64 + r] = k4.x;
            Kt[(cc + 1) * 64 + r] = k4.y;
            Kt[(cc + 2) * 64 + r] = k4.z;
            Kt[(cc + 3) * 64 + r] = k4.w;
            float4 v4 = *(const float4*)(Vh + (size_t)(kb * 64 + r) * CC + cc);
            *(float4*)(Vs + r * 128 + cc) = v4;
        }
        __syncthreads();

        // S[64][64] = Q K^T (scaled)
        float s[4][4];
#pragma unroll
        for (int i = 0; i < 4; i++)
#pragma unroll
            for (int j = 0; j < 4; j++) s[i][j] = 0.f;
#pragma unroll 8
        for (int kk = 0; kk < 128; kk++) {
            float ra[4], rb[4];
#pragma unroll
            for (int i = 0; i < 4; i++) ra[i] = Qt[kk * 64 + rG + i];
#pragma unroll
            for (int j = 0; j < 4; j++) rb[j] = Kt[kk * 64 + cG4 + j];
#pragma unroll
            for (int i = 0; i < 4; i++)
#pragma unroll
                for (int j = 0; j < 4; j++)
                    s[i][j] = fmaf(ra[i], rb[j], s[i][j]);
        }
        const bool diag = (kb == qb);
#pragma unroll
        for (int i = 0; i < 4; i++)
#pragma unroll
            for (int j = 0; j < 4; j++) {
                float vls = s[i][j];
                if (diag && (cG4 + j) > (rG + i)) vls = -1e30f;
                Ss[(rG + i) * 65 + cG4 + j] = vls;
            }
        __syncthreads();

        // Online softmax row update (4 threads per row)
        {
            int r = tid >> 2, q4i = tid & 3;
            float mx = -1e30f;
            for (int ci = q4i; ci < 64; ci += 4) mx = fmaxf(mx, Ss[r * 65 + ci]);
            mx = fmaxf(mx, __shfl_xor_sync(0xffffffffu, mx, 1));
            mx = fmaxf(mx, __shfl_xor_sync(0xffffffffu, mx, 2));
            float mold = m_s[r];
            float mnew = fmaxf(mold, mx);
            float ps = 0.f;
            for (int ci = q4i; ci < 64; ci += 4) {
                float p = __expf(Ss[r * 65 + ci] - mnew);
                Ss[r * 65 + ci] = p;
                ps += p;
            }
            ps += __shfl_xor_sync(0xffffffffu, ps, 1);
            ps += __shfl_xor_sync(0xffffffffu, ps, 2);
            if (q4i == 0) {
                float al = __expf(mold - mnew);
                al_s[r] = al;
                m_s[r] = mnew;
                l_s[r] = l_s[r] * al + ps;
            }
        }
        __syncthreads();

        // Rescale accumulators, then O += P @ V
        float av[4];
#pragma unroll
        for (int i = 0; i < 4; i++) av[i] = al_s[rG + i];
#pragma unroll
        for (int i = 0; i < 4; i++)
#pragma unroll
            for (int j = 0; j < 8; j++) o[i][j] *= av[i];
#pragma unroll 8
        for (int ss2 = 0; ss2 < 64; ss2++) {
            float rp[4], rv[8];
#pragma unroll
            for (int i = 0; i < 4; i++) rp[i] = Ss[(rG + i) * 65 + ss2];
#pragma unroll
            for (int j = 0; j < 8; j++) rv[j] = Vs[ss2 * 128 + cG8 + j];
#pragma unroll
            for (int i = 0; i < 4; i++)
#pragma unroll
                for (int j = 0; j < 8; j++)
                    o[i][j] = fmaf(rp[i], rv[j], o[i][j]);
        }
    }

    // Final normalize + store to [T][D]
#pragma unroll
    for (int i = 0; i < 4; i++) {
        float invl = 1.f / l_s[rG + i];
        float* orow = Og + (size_t)(qm0 + rG + i) * DD + h * CC + cG8;
#pragma unroll
        for (int j = 0; j < 8; j++) orow[j] = o[i][j] * invl;
    }
}

// ---------------------------------------------------------------------------
// Launch: qkv GEMM -> ln/rope/split -> flash attention -> proj GEMM
// ---------------------------------------------------------------------------
extern "C" void kernel_launch(void* const* d_in, const int* in_sizes, int n_in,
                              void* d_out, int out_size)
{
    const float* x  = (const float*)d_in[0];
    const float* Wa = (const float*)d_in[1];
    const float* ba = (const float*)d_in[2];
    const float* Wp = (const float*)d_in[3];
    const float* bp = (const float*)d_in[4];
    const float* qw = (const float*)d_in[5];
    const float* kw = (const float*)d_in[6];
    float* out = (float*)d_out;

    float *qkv, *q, *k, *v, *att;
    cudaGetSymbolAddress((void**)&qkv, g_qkv);
    cudaGetSymbolAddress((void**)&q,   g_q);
    cudaGetSymbolAddress((void**)&k,   g_k);
    cudaGetSymbolAddress((void**)&v,   g_v);
    cudaGetSymbolAddress((void**)&att, g_att);

    // 1) qkv = x @ W_attn^T + b_attn   [2048, 6144]
    sgemm_nt_bias<<<dim3(D3 / 128, TT / 128), 256>>>(x, Wa, ba, qkv, TT, D3, DD);

    // 2) per-head LN + RoPE + split/relayout
    ln_rope_split<<<dim3(TT, HH), 128>>>(qkv, qw, kw, q, k, v);

    // 3) causal flash attention -> att[T][D]
    cudaFuncSetAttribute(flash_attn, cudaFuncAttributeMaxDynamicSharedMemorySize, FA_SMEM);
    flash_attn<<<dim3(TT / 64, HH), 256, FA_SMEM>>>(q, k, v, att);

    // 4) out = att @ W_proj^T + b_proj
    sgemm_nt_bias<<<dim3(DD / 128, TT / 128), 256>>>(att, Wp, bp, out, TT, DD, DD);
}

// round 6
// speedup vs baseline: 1.2008x; 1.2008x over previous
#include <cuda_runtime.h>
#include <cstdint>

// Problem constants
#define TT 2048
#define DD 2048
#define HH 16
#define CC 128
#define D3 6144

// ---------------------------------------------------------------------------
// Scratch — EXACTLY the R1 set (the configuration known to run end-to-end)
// ---------------------------------------------------------------------------
__device__ float g_qkv[(size_t)TT * D3];        // 50 MB
__device__ float g_q[(size_t)HH * TT * CC];     // 16 MB  [H][T][C]
__device__ float g_k[(size_t)HH * TT * CC];     // 16 MB
__device__ float g_v[(size_t)HH * TT * CC];     // 16 MB
__device__ float g_att[(size_t)TT * DD];        // 16 MB  [T][D]

// ---------------------------------------------------------------------------
// Helpers
// ---------------------------------------------------------------------------
__device__ __forceinline__ float tf32_rn(float x) {
    uint32_t u;
    asm("cvt.rna.tf32.f32 %0, %1;" : "=r"(u) : "f"(x));
    return __uint_as_float(u);
}
__device__ __forceinline__ void mma_tf32(
    float& c0, float& c1, float& c2, float& c3,
    uint32_t a0, uint32_t a1, uint32_t a2, uint32_t a3,
    uint32_t b0, uint32_t b1)
{
    asm volatile(
        "mma.sync.aligned.m16n8k8.row.col.f32.tf32.tf32.f32 "
        "{%0,%1,%2,%3}, {%4,%5,%6,%7}, {%8,%9}, {%0,%1,%2,%3};"
        : "+f"(c0), "+f"(c1), "+f"(c2), "+f"(c3)
        : "r"(a0), "r"(a1), "r"(a2), "r"(a3), "r"(b0), "r"(b1));
}

// ---------------------------------------------------------------------------
// 3xTF32 mma.sync GEMM (NT): C = A @ B^T + bias, near-fp32 accuracy.
// A,B are plain fp32 in global; the big/small tf32 split is computed in
// registers during smem staging (no extra buffers, no pre-pass kernels).
// acc += Ab*Bb + Ab*Bs + As*Bb   (As*Bs ~2^-22, dropped)
// CTA 128x128, BK=16, 8 warps (4m x 2n), warp tile 32x64.
// Double-buffered LDG->regs->STS, one __syncthreads per iter.
// Smem: 4 arrays [128][20] per stage, 2 stages = 80 KB (stride 20 floats =>
// fragment fetch bank = (4r + c) mod 32, conflict-free).
// ---------------------------------------------------------------------------
#define BM 128
#define BN 128
#define BK 16
#define PADK 20
#define MAT_FLOATS (BM * PADK)                 // 2560
#define STAGE_FLOATS (4 * MAT_FLOATS)          // 10240
#define GEMM_SMEM (2 * STAGE_FLOATS * 4)       // 81920 B

__global__ __launch_bounds__(256, 2) void gemm_3xtf32(
    const float* __restrict__ A, const float* __restrict__ B,
    const float* __restrict__ bias, float* __restrict__ C,
    int M, int N, int K)
{
    extern __shared__ float sh[];
    const int tid = threadIdx.x;
    const int wid = tid >> 5, lane = tid & 31;
    const int warp_m = wid & 3;          // 4 warps along M, 32 rows each
    const int warp_n = wid >> 2;         // 2 warps along N, 64 cols each
    const int m0 = blockIdx.y * BM;
    const int n0 = blockIdx.x * BN;
    const int gr = lane >> 2, gc = lane & 3;

    float acc[2][8][4];
#pragma unroll
    for (int mt = 0; mt < 2; mt++)
#pragma unroll
        for (int nt = 0; nt < 8; nt++)
#pragma unroll
            for (int c = 0; c < 4; c++) acc[mt][nt][c] = 0.f;

    // Loader: 512 float4 slots per tile; q = tid + p*256
    // row = q>>2 (0..127), c4 = (q&3)*4
    float4 ra[2], rb[2];

    auto ldg = [&](int it) {
        const int k0 = it * BK;
#pragma unroll
        for (int p = 0; p < 2; p++) {
            int q = tid + p * 256;
            int row = q >> 2, c4 = (q & 3) << 2;
            ra[p] = *(const float4*)(A + (size_t)(m0 + row) * K + k0 + c4);
            rb[p] = *(const float4*)(B + (size_t)(n0 + row) * K + k0 + c4);
        }
    };
    auto sts = [&](int buf) {
        float* sAb = sh + buf * STAGE_FLOATS;
        float* sAs = sAb + MAT_FLOATS;
        float* sBb = sAs + MAT_FLOATS;
        float* sBs = sBb + MAT_FLOATS;
#pragma unroll
        for (int p = 0; p < 2; p++) {
            int q = tid + p * 256;
            int row = q >> 2, c4 = (q & 3) << 2;
            int o = row * PADK + c4;
            float4 b, s;
            b.x = tf32_rn(ra[p].x); s.x = tf32_rn(ra[p].x - b.x);
            b.y = tf32_rn(ra[p].y); s.y = tf32_rn(ra[p].y - b.y);
            b.z = tf32_rn(ra[p].z); s.z = tf32_rn(ra[p].z - b.z);
            b.w = tf32_rn(ra[p].w); s.w = tf32_rn(ra[p].w - b.w);
            *(float4*)(sAb + o) = b;
            *(float4*)(sAs + o) = s;
            b.x = tf32_rn(rb[p].x); s.x = tf32_rn(rb[p].x - b.x);
            b.y = tf32_rn(rb[p].y); s.y = tf32_rn(rb[p].y - b.y);
            b.z = tf32_rn(rb[p].z); s.z = tf32_rn(rb[p].z - b.z);
            b.w = tf32_rn(rb[p].w); s.w = tf32_rn(rb[p].w - b.w);
            *(float4*)(sBb + o) = b;
            *(float4*)(sBs + o) = s;
        }
    };

    const int NK = K / BK;               // 128
    ldg(0);
    sts(0);
    __syncthreads();

    for (int it = 0; it < NK; it++) {
        if (it + 1 < NK) ldg(it + 1);    // overlap global latency with compute

        const float* sAb = sh + (it & 1) * STAGE_FLOATS;
        const float* sAs = sAb + MAT_FLOATS;
        const float* sBb = sAs + MAT_FLOATS;
        const float* sBs = sBb + MAT_FLOATS;
#pragma unroll
        for (int ks = 0; ks < 2; ks++) {
            const int k0 = ks * 8;
            uint32_t ab[2][4], as_[2][4];
#pragma unroll
            for (int mt = 0; mt < 2; mt++) {
                int r = warp_m * 32 + mt * 16 + gr;
                int o0 = r * PADK + k0 + gc, o1 = (r + 8) * PADK + k0 + gc;
                ab[mt][0]  = __float_as_uint(sAb[o0]);
                ab[mt][1]  = __float_as_uint(sAb[o1]);
                ab[mt][2]  = __float_as_uint(sAb[o0 + 4]);
                ab[mt][3]  = __float_as_uint(sAb[o1 + 4]);
                as_[mt][0] = __float_as_uint(sAs[o0]);
                as_[mt][1] = __float_as_uint(sAs[o1]);
                as_[mt][2] = __float_as_uint(sAs[o0 + 4]);
                as_[mt][3] = __float_as_uint(sAs[o1 + 4]);
            }
#pragma unroll
            for (int nt = 0; nt < 8; nt++) {
                int n = warp_n * 64 + nt * 8 + gr;
                int ob = n * PADK + k0 + gc;
                uint32_t bb0 = __float_as_uint(sBb[ob]);
                uint32_t bb1 = __float_as_uint(sBb[ob + 4]);
                uint32_t bs0 = __float_as_uint(sBs[ob]);
                uint32_t bs1 = __float_as_uint(sBs[ob + 4]);
#pragma unroll
                for (int mt = 0; mt < 2; mt++) {
                    mma_tf32(acc[mt][nt][0], acc[mt][nt][1],
                             acc[mt][nt][2], acc[mt][nt][3],
                             ab[mt][0], ab[mt][1], ab[mt][2], ab[mt][3],
                             bb0, bb1);
                    mma_tf32(acc[mt][nt][0], acc[mt][nt][1],
                             acc[mt][nt][2], acc[mt][nt][3],
                             ab[mt][0], ab[mt][1], ab[mt][2], ab[mt][3],
                             bs0, bs1);
                    mma_tf32(acc[mt][nt][0], acc[mt][nt][1],
                             acc[mt][nt][2], acc[mt][nt][3],
                             as_[mt][0], as_[mt][1], as_[mt][2], as_[mt][3],
                             bb0, bb1);
                }
            }
        }

        // Write NEXT tile into the other buffer (read last before the
        // previous barrier — safe), then one barrier for the whole iter.
        if (it + 1 < NK) sts((it + 1) & 1);
        __syncthreads();
    }

    // Epilogue: c0:(r, 2gc) c1:(r, 2gc+1) c2:(r+8, 2gc) c3:(r+8, 2gc+1)
#pragma unroll
    for (int mt = 0; mt < 2; mt++) {
        int r = m0 + warp_m * 32 + mt * 16 + gr;
#pragma unroll
        for (int nt = 0; nt < 8; nt++) {
            int c = n0 + warp_n * 64 + nt * 8 + gc * 2;
            float b0 = bias[c], b1 = bias[c + 1];
            float2 lo = make_float2(acc[mt][nt][0] + b0, acc[mt][nt][1] + b1);
            float2 hi = make_float2(acc[mt][nt][2] + b0, acc[mt][nt][3] + b1);
            *(float2*)(C + (size_t)r * N + c) = lo;
            *(float2*)(C + (size_t)(r + 8) * N + c) = hi;
        }
    }
}

// ---------------------------------------------------------------------------
// Per-(t,h): layernorm over C=128 for q and k, RoPE, split + relayout (fp32)
// ---------------------------------------------------------------------------
__global__ __launch_bounds__(128) void ln_rope_split(
    const float* __restrict__ qkv,
    const float* __restrict__ qw, const float* __restrict__ kw,
    float* __restrict__ Qo, float* __restrict__ Ko, float* __restrict__ Vo)
{
    const int t = blockIdx.x, h = blockIdx.y, c = threadIdx.x;
    const float* row = qkv + (size_t)t * D3 + h * CC;
    float qv = row[c];
    float kv = row[DD + c];
    float vv = row[2 * DD + c];

    float s0 = qv, s1 = qv * qv, s2 = kv, s3 = kv * kv;
#pragma unroll
    for (int o = 16; o > 0; o >>= 1) {
        s0 += __shfl_xor_sync(0xffffffffu, s0, o);
        s1 += __shfl_xor_sync(0xffffffffu, s1, o);
        s2 += __shfl_xor_sync(0xffffffffu, s2, o);
        s3 += __shfl_xor_sync(0xffffffffu, s3, o);
    }
    __shared__ float red[4][4];
    __shared__ float sn[2][128];
    if ((c & 31) == 0) {
        int w = c >> 5;
        red[w][0] = s0; red[w][1] = s1; red[w][2] = s2; red[w][3] = s3;
    }
    __syncthreads();
    float qs  = red[0][0] + red[1][0] + red[2][0] + red[3][0];
    float qss = red[0][1] + red[1][1] + red[2][1] + red[3][1];
    float ks  = red[0][2] + red[1][2] + red[2][2] + red[3][2];
    float kss = red[0][3] + red[1][3] + red[2][3] + red[3][3];

    const float inv128 = 1.f / 128.f;
    float qmu = qs * inv128, kmu = ks * inv128;
    float qvar = qss * inv128 - qmu * qmu;
    float kvar = kss * inv128 - kmu * kmu;
    float qr = rsqrtf(qvar + 1e-6f);
    float kr = rsqrtf(kvar + 1e-6f);
    float qn = (qv - qmu) * qr * qw[c];
    float kn = (kv - kmu) * kr * kw[c];
    sn[0][c] = qn;
    sn[1][c] = kn;
    __syncthreads();

    int i = c >> 1;
    float inv = __powf(10000.f, -(float)(2 * i) * (1.f / 128.f));
    float fr = (float)t * inv;
    float sf, cf;
    sincosf(fr, &sf, &cf);
    float qp = sn[0][c ^ 1], kp = sn[1][c ^ 1];
    float qo = (c & 1) ? fmaf(qn, cf, qp * sf) : fmaf(qn, cf, -qp * sf);
    float ko = (c & 1) ? fmaf(kn, cf, kp * sf) : fmaf(kn, cf, -kp * sf);

    size_t oidx = ((size_t)h * TT + t) * CC + c;
    Qo[oidx] = qo;
    Ko[oidx] = ko;
    Vo[oidx] = vv;
}

// ---------------------------------------------------------------------------
// Causal flash attention, fp32 FFMA (known-good R1 kernel, unchanged)
// ---------------------------------------------------------------------------
#define FA_SMEM ((128 * 64 + 128 * 64 + 64 * 128 + 64 * 65) * 4)

__global__ __launch_bounds__(256) void flash_attn(
    const float* __restrict__ Qg, const float* __restrict__ Kg,
    const float* __restrict__ Vg, float* __restrict__ Og)
{
    extern __shared__ float sm[];
    float* Qt = sm;
    float* Kt = Qt + 128 * 64;
    float* Vs = Kt + 128 * 64;
    float* Ss = Vs + 64 * 128;
    __shared__ float m_s[64], l_s[64], al_s[64];

    const int tid = threadIdx.x;
    const int qb = blockIdx.x, h = blockIdx.y;
    const int qm0 = qb * 64;
    const float* Qh = Qg + (size_t)h * TT * CC;
    const float* Kh = Kg + (size_t)h * TT * CC;
    const float* Vh = Vg + (size_t)h * TT * CC;
    const float scale = 0.08838834764831845f;

#pragma unroll
    for (int i = 0; i < 8; i++) {
        int id = tid + i * 256;
        int r = id >> 5, cc = (id & 31) << 2;
        float4 q4 = *(const float4*)(Qh + (size_t)(qm0 + r) * CC + cc);
        Qt[(cc + 0) * 64 + r] = q4.x * scale;
        Qt[(cc + 1) * 64 + r] = q4.y * scale;
        Qt[(cc + 2) * 64 + r] = q4.z * scale;
        Qt[(cc + 3) * 64 + r] = q4.w * scale;
    }
    if (tid < 64) { m_s[tid] = -1e30f; l_s[tid] = 0.f; }

    float o[4][8];
#pragma unroll
    for (int i = 0; i < 4; i++)
#pragma unroll
        for (int j = 0; j < 8; j++) o[i][j] = 0.f;

    const int rG  = (tid >> 4) << 2;
    const int cG4 = (tid & 15) << 2;
    const int cG8 = (tid & 15) << 3;

    for (int kb = 0; kb <= qb; kb++) {
        __syncthreads();
#pragma unroll
        for (int i = 0; i < 8; i++) {
            int id = tid + i * 256;
            int r = id >> 5, cc = (id & 31) << 2;
            float4 k4 = *(const float4*)(Kh + (size_t)(kb * 64 + r) * CC + cc);
            Kt[(cc + 0) * 64 + r] = k4.x;
            Kt[(cc + 1) * 64 + r] = k4.y;
            Kt[(cc + 2) * 64 + r] = k4.z;
            Kt[(cc + 3) * 64 + r] = k4.w;
            float4 v4 = *(const float4*)(Vh + (size_t)(kb * 64 + r) * CC + cc);
            *(float4*)(Vs + r * 128 + cc) = v4;
        }
        __syncthreads();

        float s[4][4];
#pragma unroll
        for (int i = 0; i < 4; i++)
#pragma unroll
            for (int j = 0; j < 4; j++) s[i][j] = 0.f;
#pragma unroll 8
        for (int kk = 0; kk < 128; kk++) {
            float ra[4], rb[4];
#pragma unroll
            for (int i = 0; i < 4; i++) ra[i] = Qt[kk * 64 + rG + i];
#pragma unroll
            for (int j = 0; j < 4; j++) rb[j] = Kt[kk * 64 + cG4 + j];
#pragma unroll
            for (int i = 0; i < 4; i++)
#pragma unroll
                for (int j = 0; j < 4; j++)
                    s[i][j] = fmaf(ra[i], rb[j], s[i][j]);
        }
        const bool diag = (kb == qb);
#pragma unroll
        for (int i = 0; i < 4; i++)
#pragma unroll
            for (int j = 0; j < 4; j++) {
                float vls = s[i][j];
                if (diag && (cG4 + j) > (rG + i)) vls = -1e30f;
                Ss[(rG + i) * 65 + cG4 + j] = vls;
            }
        __syncthreads();

        {
            int r = tid >> 2, q4i = tid & 3;
            float mx = -1e30f;
            for (int ci = q4i; ci < 64; ci += 4) mx = fmaxf(mx, Ss[r * 65 + ci]);
            mx = fmaxf(mx, __shfl_xor_sync(0xffffffffu, mx, 1));
            mx = fmaxf(mx, __shfl_xor_sync(0xffffffffu, mx, 2));
            float mold = m_s[r];
            float mnew = fmaxf(mold, mx);
            float ps = 0.f;
            for (int ci = q4i; ci < 64; ci += 4) {
                float p = __expf(Ss[r * 65 + ci] - mnew);
                Ss[r * 65 + ci] = p;
                ps += p;
            }
            ps += __shfl_xor_sync(0xffffffffu, ps, 1);
            ps += __shfl_xor_sync(0xffffffffu, ps, 2);
            if (q4i == 0) {
                float al = __expf(mold - mnew);
                al_s[r] = al;
                m_s[r] = mnew;
                l_s[r] = l_s[r] * al + ps;
            }
        }
        __syncthreads();

        float av[4];
#pragma unroll
        for (int i = 0; i < 4; i++) av[i] = al_s[rG + i];
#pragma unroll
        for (int i = 0; i < 4; i++)
#pragma unroll
            for (int j = 0; j < 8; j++) o[i][j] *= av[i];
#pragma unroll 8
        for (int ss2 = 0; ss2 < 64; ss2++) {
            float rp[4], rv[8];
#pragma unroll
            for (int i = 0; i < 4; i++) rp[i] = Ss[(rG + i) * 65 + ss2];
#pragma unroll
            for (int j = 0; j < 8; j++) rv[j] = Vs[ss2 * 128 + cG8 + j];
#pragma unroll
            for (int i = 0; i < 4; i++)
#pragma unroll
                for (int j = 0; j < 8; j++)
                    o[i][j] = fmaf(rp[i], rv[j], o[i][j]);
        }
    }

#pragma unroll
    for (int i = 0; i < 4; i++) {
        float invl = 1.f / l_s[rG + i];
        float* orow = Og + (size_t)(qm0 + rG + i) * DD + h * CC + cG8;
#pragma unroll
        for (int j = 0; j < 8; j++) orow[j] = o[i][j] * invl;
    }
}

// ---------------------------------------------------------------------------
// Launch — same 4-kernel sequence as R1
// ---------------------------------------------------------------------------
extern "C" void kernel_launch(void* const* d_in, const int* in_sizes, int n_in,
                              void* d_out, int out_size)
{
    const float* x  = (const float*)d_in[0];
    const float* Wa = (const float*)d_in[1];
    const float* ba = (const float*)d_in[2];
    const float* Wp = (const float*)d_in[3];
    const float* bp = (const float*)d_in[4];
    const float* qw = (const float*)d_in[5];
    const float* kw = (const float*)d_in[6];
    float* out = (float*)d_out;

    float *qkv, *q, *k, *v, *att;
    cudaGetSymbolAddress((void**)&qkv, g_qkv);
    cudaGetSymbolAddress((void**)&q,   g_q);
    cudaGetSymbolAddress((void**)&k,   g_k);
    cudaGetSymbolAddress((void**)&v,   g_v);
    cudaGetSymbolAddress((void**)&att, g_att);

    cudaFuncSetAttribute(gemm_3xtf32, cudaFuncAttributeMaxDynamicSharedMemorySize, GEMM_SMEM);
    cudaFuncSetAttribute(flash_attn, cudaFuncAttributeMaxDynamicSharedMemorySize, FA_SMEM);

    // 1) qkv = x @ W_attn^T + b_attn  (3xTF32 mma.sync, inline split)
    gemm_3xtf32<<<dim3(D3 / BN, TT / BM), 256, GEMM_SMEM>>>(
        x, Wa, ba, qkv, TT, D3, DD);

    // 2) LN + RoPE + split
    ln_rope_split<<<dim3(TT, HH), 128>>>(qkv, qw, kw, q, k, v);

    // 3) causal flash attention (fp32)
    flash_attn<<<dim3(TT / 64, HH), 256, FA_SMEM>>>(q, k, v, att);

    // 4) out = att @ W_proj^T + b_proj  (3xTF32 mma.sync, inline split)
    gemm_3xtf32<<<dim3(DD / BN, TT / BM), 256, GEMM_SMEM>>>(
        att, Wp, bp, out, TT, DD, DD);
}

// round 8
// speedup vs baseline: 1.9307x; 1.6078x over previous
#include <cuda_runtime.h>
#include <cstdint>

// Problem constants
#define TT 2048
#define DD 2048
#define HH 16
#define CC 128
#define D3 6144

// ---------------------------------------------------------------------------
// Scratch — R1-proven set
// ---------------------------------------------------------------------------
__device__ float g_qkv[(size_t)TT * D3];        // 50 MB
__device__ float g_q[(size_t)HH * TT * CC];     // 16 MB  [H][T][C] (tf32, pre-scaled)
__device__ float g_k[(size_t)HH * TT * CC];     // 16 MB  (tf32)
__device__ float g_v[(size_t)HH * TT * CC];     // 16 MB  (tf32)
__device__ float g_att[(size_t)TT * DD];        // 16 MB  [T][D]

// ---------------------------------------------------------------------------
// Helpers
// ---------------------------------------------------------------------------
__device__ __forceinline__ float tf32_rn(float x) {
    uint32_t u;
    asm("cvt.rna.tf32.f32 %0, %1;" : "=r"(u) : "f"(x));
    return __uint_as_float(u);
}
__device__ __forceinline__ void mma_tf32(
    float& c0, float& c1, float& c2, float& c3,
    uint32_t a0, uint32_t a1, uint32_t a2, uint32_t a3,
    uint32_t b0, uint32_t b1)
{
    asm volatile(
        "mma.sync.aligned.m16n8k8.row.col.f32.tf32.tf32.f32 "
        "{%0,%1,%2,%3}, {%4,%5,%6,%7}, {%8,%9}, {%0,%1,%2,%3};"
        : "+f"(c0), "+f"(c1), "+f"(c2), "+f"(c3)
        : "r"(a0), "r"(a1), "r"(a2), "r"(a3), "r"(b0), "r"(b1));
}

// ---------------------------------------------------------------------------
// 3xTF32 mma.sync GEMM (NT) — unchanged from R6 (known-good)
// ---------------------------------------------------------------------------
#define BM 128
#define BN 128
#define BK 16
#define PADK 20
#define MAT_FLOATS (BM * PADK)
#define STAGE_FLOATS (4 * MAT_FLOATS)
#define GEMM_SMEM (2 * STAGE_FLOATS * 4)

__global__ __launch_bounds__(256, 2) void gemm_3xtf32(
    const float* __restrict__ A, const float* __restrict__ B,
    const float* __restrict__ bias, float* __restrict__ C,
    int M, int N, int K)
{
    extern __shared__ float sh[];
    const int tid = threadIdx.x;
    const int wid = tid >> 5, lane = tid & 31;
    const int warp_m = wid & 3;
    const int warp_n = wid >> 2;
    const int m0 = blockIdx.y * BM;
    const int n0 = blockIdx.x * BN;
    const int gr = lane >> 2, gc = lane & 3;

    float acc[2][8][4];
#pragma unroll
    for (int mt = 0; mt < 2; mt++)
#pragma unroll
        for (int nt = 0; nt < 8; nt++)
#pragma unroll
            for (int c = 0; c < 4; c++) acc[mt][nt][c] = 0.f;

    float4 ra[2], rb[2];
    auto ldg = [&](int it) {
        const int k0 = it * BK;
#pragma unroll
        for (int p = 0; p < 2; p++) {
            int q = tid + p * 256;
            int row = q >> 2, c4 = (q & 3) << 2;
            ra[p] = *(const float4*)(A + (size_t)(m0 + row) * K + k0 + c4);
            rb[p] = *(const float4*)(B + (size_t)(n0 + row) * K + k0 + c4);
        }
    };
    auto sts = [&](int buf) {
        float* sAb = sh + buf * STAGE_FLOATS;
        float* sAs = sAb + MAT_FLOATS;
        float* sBb = sAs + MAT_FLOATS;
        float* sBs = sBb + MAT_FLOATS;
#pragma unroll
        for (int p = 0; p < 2; p++) {
            int q = tid + p * 256;
            int row = q >> 2, c4 = (q & 3) << 2;
            int o = row * PADK + c4;
            float4 b, s;
            b.x = tf32_rn(ra[p].x); s.x = tf32_rn(ra[p].x - b.x);
            b.y = tf32_rn(ra[p].y); s.y = tf32_rn(ra[p].y - b.y);
            b.z = tf32_rn(ra[p].z); s.z = tf32_rn(ra[p].z - b.z);
            b.w = tf32_rn(ra[p].w); s.w = tf32_rn(ra[p].w - b.w);
            *(float4*)(sAb + o) = b;
            *(float4*)(sAs + o) = s;
            b.x = tf32_rn(rb[p].x); s.x = tf32_rn(rb[p].x - b.x);
            b.y = tf32_rn(rb[p].y); s.y = tf32_rn(rb[p].y - b.y);
            b.z = tf32_rn(rb[p].z); s.z = tf32_rn(rb[p].z - b.z);
            b.w = tf32_rn(rb[p].w); s.w = tf32_rn(rb[p].w - b.w);
            *(float4*)(sBb + o) = b;
            *(float4*)(sBs + o) = s;
        }
    };

    const int NK = K / BK;
    ldg(0);
    sts(0);
    __syncthreads();

    for (int it = 0; it < NK; it++) {
        if (it + 1 < NK) ldg(it + 1);

        const float* sAb = sh + (it & 1) * STAGE_FLOATS;
        const float* sAs = sAb + MAT_FLOATS;
        const float* sBb = sAs + MAT_FLOATS;
        const float* sBs = sBb + MAT_FLOATS;
#pragma unroll
        for (int ks = 0; ks < 2; ks++) {
            const int k0 = ks * 8;
            uint32_t ab[2][4], as_[2][4];
#pragma unroll
            for (int mt = 0; mt < 2; mt++) {
                int r = warp_m * 32 + mt * 16 + gr;
                int o0 = r * PADK + k0 + gc, o1 = (r + 8) * PADK + k0 + gc;
                ab[mt][0]  = __float_as_uint(sAb[o0]);
                ab[mt][1]  = __float_as_uint(sAb[o1]);
                ab[mt][2]  = __float_as_uint(sAb[o0 + 4]);
                ab[mt][3]  = __float_as_uint(sAb[o1 + 4]);
                as_[mt][0] = __float_as_uint(sAs[o0]);
                as_[mt][1] = __float_as_uint(sAs[o1]);
                as_[mt][2] = __float_as_uint(sAs[o0 + 4]);
                as_[mt][3] = __float_as_uint(sAs[o1 + 4]);
            }
#pragma unroll
            for (int nt = 0; nt < 8; nt++) {
                int n = warp_n * 64 + nt * 8 + gr;
                int ob = n * PADK + k0 + gc;
                uint32_t bb0 = __float_as_uint(sBb[ob]);
                uint32_t bb1 = __float_as_uint(sBb[ob + 4]);
                uint32_t bs0 = __float_as_uint(sBs[ob]);
                uint32_t bs1 = __float_as_uint(sBs[ob + 4]);
#pragma unroll
                for (int mt = 0; mt < 2; mt++) {
                    mma_tf32(acc[mt][nt][0], acc[mt][nt][1],
                             acc[mt][nt][2], acc[mt][nt][3],
                             ab[mt][0], ab[mt][1], ab[mt][2], ab[mt][3],
                             bb0, bb1);
                    mma_tf32(acc[mt][nt][0], acc[mt][nt][1],
                             acc[mt][nt][2], acc[mt][nt][3],
                             ab[mt][0], ab[mt][1], ab[mt][2], ab[mt][3],
                             bs0, bs1);
                    mma_tf32(acc[mt][nt][0], acc[mt][nt][1],
                             acc[mt][nt][2], acc[mt][nt][3],
                             as_[mt][0], as_[mt][1], as_[mt][2], as_[mt][3],
                             bb0, bb1);
                }
            }
        }
        if (it + 1 < NK) sts((it + 1) & 1);
        __syncthreads();
    }

#pragma unroll
    for (int mt = 0; mt < 2; mt++) {
        int r = m0 + warp_m * 32 + mt * 16 + gr;
#pragma unroll
        for (int nt = 0; nt < 8; nt++) {
            int c = n0 + warp_n * 64 + nt * 8 + gc * 2;
            float b0 = bias[c], b1 = bias[c + 1];
            float2 lo = make_float2(acc[mt][nt][0] + b0, acc[mt][nt][1] + b1);
            float2 hi = make_float2(acc[mt][nt][2] + b0, acc[mt][nt][3] + b1);
            *(float2*)(C + (size_t)r * N + c) = lo;
            *(float2*)(C + (size_t)(r + 8) * N + c) = hi;
        }
    }
}

// ---------------------------------------------------------------------------
// LN + RoPE + split; outputs tf32-rounded (q pre-scaled by 1/sqrt(C))
// ---------------------------------------------------------------------------
__global__ __launch_bounds__(128) void ln_rope_split(
    const float* __restrict__ qkv,
    const float* __restrict__ qw, const float* __restrict__ kw,
    float* __restrict__ Qo, float* __restrict__ Ko, float* __restrict__ Vo)
{
    const int t = blockIdx.x, h = blockIdx.y, c = threadIdx.x;
    const float* row = qkv + (size_t)t * D3 + h * CC;
    float qv = row[c];
    float kv = row[DD + c];
    float vv = row[2 * DD + c];

    float s0 = qv, s1 = qv * qv, s2 = kv, s3 = kv * kv;
#pragma unroll
    for (int o = 16; o > 0; o >>= 1) {
        s0 += __shfl_xor_sync(0xffffffffu, s0, o);
        s1 += __shfl_xor_sync(0xffffffffu, s1, o);
        s2 += __shfl_xor_sync(0xffffffffu, s2, o);
        s3 += __shfl_xor_sync(0xffffffffu, s3, o);
    }
    __shared__ float red[4][4];
    __shared__ float sn[2][128];
    if ((c & 31) == 0) {
        int w = c >> 5;
        red[w][0] = s0; red[w][1] = s1; red[w][2] = s2; red[w][3] = s3;
    }
    __syncthreads();
    float qs  = red[0][0] + red[1][0] + red[2][0] + red[3][0];
    float qss = red[0][1] + red[1][1] + red[2][1] + red[3][1];
    float ks  = red[0][2] + red[1][2] + red[2][2] + red[3][2];
    float kss = red[0][3] + red[1][3] + red[2][3] + red[3][3];

    const float inv128 = 1.f / 128.f;
    float qmu = qs * inv128, kmu = ks * inv128;
    float qvar = qss * inv128 - qmu * qmu;
    float kvar = kss * inv128 - kmu * kmu;
    float qr = rsqrtf(qvar + 1e-6f);
    float kr = rsqrtf(kvar + 1e-6f);
    float qn = (qv - qmu) * qr * qw[c];
    float kn = (kv - kmu) * kr * kw[c];
    sn[0][c] = qn;
    sn[1][c] = kn;
    __syncthreads();

    int i = c >> 1;
    float inv = __powf(10000.f, -(float)(2 * i) * (1.f / 128.f));
    float fr = (float)t * inv;
    float sf, cf;
    sincosf(fr, &sf, &cf);
    float qp = sn[0][c ^ 1], kp = sn[1][c ^ 1];
    float qo = (c & 1) ? fmaf(qn, cf, qp * sf) : fmaf(qn, cf, -qp * sf);
    float ko = (c & 1) ? fmaf(kn, cf, kp * sf) : fmaf(kn, cf, -kp * sf);

    const float scale = 0.08838834764831845f;  // 1/sqrt(128)
    size_t oidx = ((size_t)h * TT + t) * CC + c;
    Qo[oidx] = tf32_rn(qo * scale);
    Ko[oidx] = tf32_rn(ko);
    Vo[oidx] = tf32_rn(vv);
}

// ---------------------------------------------------------------------------
// Causal flash attention with mma.sync tf32.
// Per CTA: 128 q rows x 1 head; kv blocks of 64; 256 threads / 8 warps.
// Warp layout: 4m x 2n. QK: warp tile 32x32 (accs[2][4][4]);
// PV/O: warp tile 32x64 (acc_o[2][8][4]).
// smem pads: Qs/Ks stride 132 (=4 mod 32), Vs stride 136 (=8 mod 32),
// Ss stride 68 (=4 mod 32)  => all fragment fetches conflict-free.
// ---------------------------------------------------------------------------
#define AQ_PAD 132
#define AK_PAD 132
#define AV_PAD 136
#define AS_PAD 68
#define ATT_SMEM ((128 * AQ_PAD + 64 * AK_PAD + 64 * AV_PAD + 128 * AS_PAD) * 4)

__global__ __launch_bounds__(256) void flash_attn_mma(
    const float* __restrict__ Qg, const float* __restrict__ Kg,
    const float* __restrict__ Vg, float* __restrict__ Og)
{
    extern __shared__ float sm[];
    float* Qs = sm;                       // [128][132]
    float* Ks = Qs + 128 * AQ_PAD;        // [64][132]
    float* Vs = Ks + 64 * AK_PAD;         // [64][136]
    float* Ss = Vs + 64 * AV_PAD;         // [128][68]
    __shared__ float m_s[128], l_s[128], al_s[128];

    const int tid = threadIdx.x;
    const int wid = tid >> 5, lane = tid & 31;
    const int warp_m = wid & 3, warp_n = wid >> 2;
    const int gr = lane >> 2, gc = lane & 3;
    const int qb = blockIdx.x, h = blockIdx.y;
    const int qm0 = qb * 128;
    const float* Qh = Qg + (size_t)h * TT * CC;
    const float* Kh = Kg + (size_t)h * TT * CC;
    const float* Vh = Vg + (size_t)h * TT * CC;

    // Load Q tile (tf32-rounded, pre-scaled already)
#pragma unroll
    for (int i = 0; i < 16; i++) {
        int q = tid + i * 256;
        int r = q >> 5, c4 = (q & 31) << 2;
        *(float4*)(Qs + r * AQ_PAD + c4) =
            *(const float4*)(Qh + (size_t)(qm0 + r) * CC + c4);
    }
    if (tid < 128) { m_s[tid] = -1e30f; l_s[tid] = 0.f; }

    float acc_o[2][8][4];
#pragma unroll
    for (int mt = 0; mt < 2; mt++)
#pragma unroll
        for (int nt = 0; nt < 8; nt++)
#pragma unroll
            for (int c = 0; c < 4; c++) acc_o[mt][nt][c] = 0.f;

    const int nkb = 2 * qb + 2;
    for (int kb = 0; kb < nkb; kb++) {
        __syncthreads();   // prev PV done with Vs/Ss; Q ready on iter 0
#pragma unroll
        for (int i = 0; i < 8; i++) {
            int q = tid + i * 256;
            int r = q >> 5, c4 = (q & 31) << 2;
            *(float4*)(Ks + r * AK_PAD + c4) =
                *(const float4*)(Kh + (size_t)(kb * 64 + r) * CC + c4);
            *(float4*)(Vs + r * AV_PAD + c4) =
                *(const float4*)(Vh + (size_t)(kb * 64 + r) * CC + c4);
        }
        __syncthreads();

        // ---- S[128][64] = Q @ K^T ----
        float accs[2][4][4];
#pragma unroll
        for (int mt = 0; mt < 2; mt++)
#pragma unroll
            for (int nt = 0; nt < 4; nt++)
#pragma unroll
                for (int c = 0; c < 4; c++) accs[mt][nt][c] = 0.f;
#pragma unroll
        for (int ks = 0; ks < 16; ks++) {
            const int k0 = ks * 8;
            uint32_t af[2][4];
#pragma unroll
            for (int mt = 0; mt < 2; mt++) {
                int r = warp_m * 32 + mt * 16 + gr;
                int o0 = r * AQ_PAD + k0 + gc, o1 = (r + 8) * AQ_PAD + k0 + gc;
                af[mt][0] = __float_as_uint(Qs[o0]);
                af[mt][1] = __float_as_uint(Qs[o1]);
                af[mt][2] = __float_as_uint(Qs[o0 + 4]);
                af[mt][3] = __float_as_uint(Qs[o1 + 4]);
            }
#pragma unroll
            for (int nt = 0; nt < 4; nt++) {
                int n = warp_n * 32 + nt * 8 + gr;
                uint32_t b0 = __float_as_uint(Ks[n * AK_PAD + k0 + gc]);
                uint32_t b1 = __float_as_uint(Ks[n * AK_PAD + k0 + 4 + gc]);
#pragma unroll
                for (int mt = 0; mt < 2; mt++)
                    mma_tf32(accs[mt][nt][0], accs[mt][nt][1],
                             accs[mt][nt][2], accs[mt][nt][3],
                             af[mt][0], af[mt][1], af[mt][2], af[mt][3],
                             b0, b1);
            }
        }

        // ---- mask (only blocks crossing the diagonal) + store S ----
        const bool need_mask = (kb >= 2 * qb);
#pragma unroll
        for (int mt = 0; mt < 2; mt++) {
            int rl = warp_m * 32 + mt * 16 + gr;
#pragma unroll
            for (int nt = 0; nt < 4; nt++) {
                int cl = warp_n * 32 + nt * 8 + 2 * gc;
                float v0 = accs[mt][nt][0], v1 = accs[mt][nt][1];
                float v2 = accs[mt][nt][2], v3 = accs[mt][nt][3];
                if (need_mask) {
                    int qg0 = qm0 + rl, qg1 = qg0 + 8;
                    int sg0 = kb * 64 + cl, sg1 = sg0 + 1;
                    if (sg0 > qg0) v0 = -1e30f;
                    if (sg1 > qg0) v1 = -1e30f;
                    if (sg0 > qg1) v2 = -1e30f;
                    if (sg1 > qg1) v3 = -1e30f;
                }
                *(float2*)(Ss + rl * AS_PAD + cl) = make_float2(v0, v1);
                *(float2*)(Ss + (rl + 8) * AS_PAD + cl) = make_float2(v2, v3);
            }
        }
        __syncthreads();

        // ---- online softmax (2 threads per row) ----
        {
            int r = tid >> 1, half = tid & 1;
            float* row = Ss + r * AS_PAD + half * 32;
            float mx = -1e30f;
#pragma unroll
            for (int j = 0; j < 32; j++) mx = fmaxf(mx, row[j]);
            mx = fmaxf(mx, __shfl_xor_sync(0xffffffffu, mx, 1));
            float mold = m_s[r];
            float mnew = fmaxf(mold, mx);
            float ps = 0.f;
#pragma unroll
            for (int j = 0; j < 32; j++) {
                float p = __expf(row[j] - mnew);
                ps += p;
                row[j] = tf32_rn(p);
            }
            ps += __shfl_xor_sync(0xffffffffu, ps, 1);
            if (half == 0) {
                float al = __expf(mold - mnew);
                al_s[r] = al;
                m_s[r] = mnew;
                l_s[r] = l_s[r] * al + ps;
            }
        }
        __syncthreads();

        // ---- rescale O, then O += P @ V ----
#pragma unroll
        for (int mt = 0; mt < 2; mt++) {
            int rl = warp_m * 32 + mt * 16 + gr;
            float a0 = al_s[rl], a1 = al_s[rl + 8];
#pragma unroll
            for (int nt = 0; nt < 8; nt++) {
                acc_o[mt][nt][0] *= a0; acc_o[mt][nt][1] *= a0;
                acc_o[mt][nt][2] *= a1; acc_o[mt][nt][3] *= a1;
            }
        }
#pragma unroll
        for (int ks = 0; ks < 8; ks++) {
            const int k0 = ks * 8;
            uint32_t af[2][4];
#pragma unroll
            for (int mt = 0; mt < 2; mt++) {
                int r = warp_m * 32 + mt * 16 + gr;
                int o0 = r * AS_PAD + k0 + gc, o1 = (r + 8) * AS_PAD + k0 + gc;
                af[mt][0] = __float_as_uint(Ss[o0]);
                af[mt][1] = __float_as_uint(Ss[o1]);
                af[mt][2] = __float_as_uint(Ss[o0 + 4]);
                af[mt][3] = __float_as_uint(Ss[o1 + 4]);
            }
#pragma unroll
            for (int nt = 0; nt < 8; nt++) {
                int n = warp_n * 64 + nt * 8 + gr;
                uint32_t b0 = __float_as_uint(Vs[(k0 + gc) * AV_PAD + n]);
                uint32_t b1 = __float_as_uint(Vs[(k0 + 4 + gc) * AV_PAD + n]);
#pragma unroll
                for (int mt = 0; mt < 2; mt++)
                    mma_tf32(acc_o[mt][nt][0], acc_o[mt][nt][1],
                             acc_o[mt][nt][2], acc_o[mt][nt][3],
                             af[mt][0], af[mt][1], af[mt][2], af[mt][3],
                             b0, b1);
            }
        }
    }

    // ---- normalize + store to [T][D] ----
#pragma unroll
    for (int mt = 0; mt < 2; mt++) {
        int rl = warp_m * 32 + mt * 16 + gr;
        float inv0 = 1.f / l_s[rl], inv1 = 1.f / l_s[rl + 8];
#pragma unroll
        for (int nt = 0; nt < 8; nt++) {
            int c = warp_n * 64 + nt * 8 + 2 * gc;
            float* r0 = Og + (size_t)(qm0 + rl) * DD + h * CC + c;
            float* r1 = Og + (size_t)(qm0 + rl + 8) * DD + h * CC + c;
            *(float2*)r0 = make_float2(acc_o[mt][nt][0] * inv0,
                                       acc_o[mt][nt][1] * inv0);
            *(float2*)r1 = make_float2(acc_o[mt][nt][2] * inv1,
                                       acc_o[mt][nt][3] * inv1);
        }
    }
}

// ---------------------------------------------------------------------------
// Launch
// ---------------------------------------------------------------------------
extern "C" void kernel_launch(void* const* d_in, const int* in_sizes, int n_in,
                              void* d_out, int out_size)
{
    const float* x  = (const float*)d_in[0];
    const float* Wa = (const float*)d_in[1];
    const float* ba = (const float*)d_in[2];
    const float* Wp = (const float*)d_in[3];
    const float* bp = (const float*)d_in[4];
    const float* qw = (const float*)d_in[5];
    const float* kw = (const float*)d_in[6];
    float* out = (float*)d_out;

    float *qkv, *q, *k, *v, *att;
    cudaGetSymbolAddress((void**)&qkv, g_qkv);
    cudaGetSymbolAddress((void**)&q,   g_q);
    cudaGetSymbolAddress((void**)&k,   g_k);
    cudaGetSymbolAddress((void**)&v,   g_v);
    cudaGetSymbolAddress((void**)&att, g_att);

    cudaFuncSetAttribute(gemm_3xtf32, cudaFuncAttributeMaxDynamicSharedMemorySize, GEMM_SMEM);
    cudaFuncSetAttribute(flash_attn_mma, cudaFuncAttributeMaxDynamicSharedMemorySize, ATT_SMEM);

    // 1) qkv = x @ W_attn^T + b_attn  (3xTF32 mma.sync)
    gemm_3xtf32<<<dim3(D3 / BN, TT / BM), 256, GEMM_SMEM>>>(
        x, Wa, ba, qkv, TT, D3, DD);

    // 2) LN + RoPE + split (tf32-rounded outputs, q pre-scaled)
    ln_rope_split<<<dim3(TT, HH), 128>>>(qkv, qw, kw, q, k, v);

    // 3) causal flash attention (tf32 mma.sync)
    flash_attn_mma<<<dim3(TT / 128, HH), 256, ATT_SMEM>>>(q, k, v, att);

    // 4) out = att @ W_proj^T + b_proj  (3xTF32 mma.sync)
    gemm_3xtf32<<<dim3(DD / BN, TT / BM), 256, GEMM_SMEM>>>(
        att, Wp, bp, out, TT, DD, DD);
}

// round 11
// speedup vs baseline: 3.4855x; 1.8053x over previous
#include <cuda_runtime.h>
#include <cstdint>

// Problem constants
#define TT 2048
#define DD 2048
#define HH 16
#define CC 128
#define D3 6144

// ---------------------------------------------------------------------------
// Scratch — R1-proven set
// ---------------------------------------------------------------------------
__device__ float g_qkv[(size_t)TT * D3];        // 50 MB
__device__ float g_q[(size_t)HH * TT * CC];     // 16 MB  [H][T][C] (tf32, pre-scaled)
__device__ float g_k[(size_t)HH * TT * CC];     // 16 MB  (tf32)
__device__ float g_v[(size_t)HH * TT * CC];     // 16 MB  (tf32)
__device__ float g_att[(size_t)TT * DD];        // 16 MB  [T][D]

// ---------------------------------------------------------------------------
// Helpers
// ---------------------------------------------------------------------------
__device__ __forceinline__ float tf32_rn(float x) {
    uint32_t u;
    asm("cvt.rna.tf32.f32 %0, %1;" : "=r"(u) : "f"(x));
    return __uint_as_float(u);
}
__device__ __forceinline__ void mma_tf32(
    float& c0, float& c1, float& c2, float& c3,
    uint32_t a0, uint32_t a1, uint32_t a2, uint32_t a3,
    uint32_t b0, uint32_t b1)
{
    asm volatile(
        "mma.sync.aligned.m16n8k8.row.col.f32.tf32.tf32.f32 "
        "{%0,%1,%2,%3}, {%4,%5,%6,%7}, {%8,%9}, {%0,%1,%2,%3};"
        : "+f"(c0), "+f"(c1), "+f"(c2), "+f"(c3)
        : "r"(a0), "r"(a1), "r"(a2), "r"(a3), "r"(b0), "r"(b1));
}

// ---------------------------------------------------------------------------
// Plain-tf32 mma.sync GEMM (NT): C = A @ B^T + bias
// CTA 128x128, BK=16, 8 warps (4m x 2n), warp tile 32x64, double buffer.
// Inline tf32 rounding during smem staging (1 cvt per float).
// Smem: A[128][20] + B[128][20] per stage, 2 stages = 40 KB.
// ---------------------------------------------------------------------------
#define BM 128
#define BN 128
#define BK 16
#define PADK 20
#define MAT_FLOATS (BM * PADK)                 // 2560
#define STAGE_FLOATS (2 * MAT_FLOATS)          // 5120
#define GEMM_SMEM (2 * STAGE_FLOATS * 4)       // 40960 B

__global__ __launch_bounds__(256, 2) void gemm_tf32p(
    const float* __restrict__ A, const float* __restrict__ B,
    const float* __restrict__ bias, float* __restrict__ C,
    int M, int N, int K)
{
    extern __shared__ float sh[];
    const int tid = threadIdx.x;
    const int wid = tid >> 5, lane = tid & 31;
    const int warp_m = wid & 3;          // 4 warps along M, 32 rows each
    const int warp_n = wid >> 2;         // 2 warps along N, 64 cols each
    const int m0 = blockIdx.y * BM;
    const int n0 = blockIdx.x * BN;
    const int gr = lane >> 2, gc = lane & 3;

    float acc[2][8][4];
#pragma unroll
    for (int mt = 0; mt < 2; mt++)
#pragma unroll
        for (int nt = 0; nt < 8; nt++)
#pragma unroll
            for (int c = 0; c < 4; c++) acc[mt][nt][c] = 0.f;

    float4 ra[2], rb[2];
    auto ldg = [&](int it) {
        const int k0 = it * BK;
#pragma unroll
        for (int p = 0; p < 2; p++) {
            int q = tid + p * 256;
            int row = q >> 2, c4 = (q & 3) << 2;
            ra[p] = *(const float4*)(A + (size_t)(m0 + row) * K + k0 + c4);
            rb[p] = *(const float4*)(B + (size_t)(n0 + row) * K + k0 + c4);
        }
    };
    auto sts = [&](int buf) {
        float* sA = sh + buf * STAGE_FLOATS;
        float* sB = sA + MAT_FLOATS;
#pragma unroll
        for (int p = 0; p < 2; p++) {
            int q = tid + p * 256;
            int row = q >> 2, c4 = (q & 3) << 2;
            int o = row * PADK + c4;
            float4 b;
            b.x = tf32_rn(ra[p].x); b.y = tf32_rn(ra[p].y);
            b.z = tf32_rn(ra[p].z); b.w = tf32_rn(ra[p].w);
            *(float4*)(sA + o) = b;
            b.x = tf32_rn(rb[p].x); b.y = tf32_rn(rb[p].y);
            b.z = tf32_rn(rb[p].z); b.w = tf32_rn(rb[p].w);
            *(float4*)(sB + o) = b;
        }
    };

    const int NK = K / BK;               // 128
    ldg(0);
    sts(0);
    __syncthreads();

    for (int it = 0; it < NK; it++) {
        if (it + 1 < NK) ldg(it + 1);    // hide global latency under compute

        const float* sA = sh + (it & 1) * STAGE_FLOATS;
        const float* sB = sA + MAT_FLOATS;
#pragma unroll
        for (int ks = 0; ks < 2; ks++) {
            const int k0 = ks * 8;
            uint32_t af[2][4];
#pragma unroll
            for (int mt = 0; mt < 2; mt++) {
                int r = warp_m * 32 + mt * 16 + gr;
                int o0 = r * PADK + k0 + gc, o1 = (r + 8) * PADK + k0 + gc;
                af[mt][0] = __float_as_uint(sA[o0]);
                af[mt][1] = __float_as_uint(sA[o1]);
                af[mt][2] = __float_as_uint(sA[o0 + 4]);
                af[mt][3] = __float_as_uint(sA[o1 + 4]);
            }
#pragma unroll
            for (int nt = 0; nt < 8; nt++) {
                int n = warp_n * 64 + nt * 8 + gr;
                int ob = n * PADK + k0 + gc;
                uint32_t b0 = __float_as_uint(sB[ob]);
                uint32_t b1 = __float_as_uint(sB[ob + 4]);
#pragma unroll
                for (int mt = 0; mt < 2; mt++)
                    mma_tf32(acc[mt][nt][0], acc[mt][nt][1],
                             acc[mt][nt][2], acc[mt][nt][3],
                             af[mt][0], af[mt][1], af[mt][2], af[mt][3],
                             b0, b1);
            }
        }
        if (it + 1 < NK) sts((it + 1) & 1);
        __syncthreads();
    }

    // Epilogue: c0:(r, 2gc) c1:(r, 2gc+1) c2:(r+8, 2gc) c3:(r+8, 2gc+1)
#pragma unroll
    for (int mt = 0; mt < 2; mt++) {
        int r = m0 + warp_m * 32 + mt * 16 + gr;
#pragma unroll
        for (int nt = 0; nt < 8; nt++) {
            int c = n0 + warp_n * 64 + nt * 8 + gc * 2;
            float b0 = bias[c], b1 = bias[c + 1];
            float2 lo = make_float2(acc[mt][nt][0] + b0, acc[mt][nt][1] + b1);
            float2 hi = make_float2(acc[mt][nt][2] + b0, acc[mt][nt][3] + b1);
            *(float2*)(C + (size_t)r * N + c) = lo;
            *(float2*)(C + (size_t)(r + 8) * N + c) = hi;
        }
    }
}

// ---------------------------------------------------------------------------
// LN + RoPE + split; outputs tf32-rounded (q pre-scaled by 1/sqrt(C))
// ---------------------------------------------------------------------------
__global__ __launch_bounds__(128) void ln_rope_split(
    const float* __restrict__ qkv,
    const float* __restrict__ qw, const float* __restrict__ kw,
    float* __restrict__ Qo, float* __restrict__ Ko, float* __restrict__ Vo)
{
    const int t = blockIdx.x, h = blockIdx.y, c = threadIdx.x;
    const float* row = qkv + (size_t)t * D3 + h * CC;
    float qv = row[c];
    float kv = row[DD + c];
    float vv = row[2 * DD + c];

    float s0 = qv, s1 = qv * qv, s2 = kv, s3 = kv * kv;
#pragma unroll
    for (int o = 16; o > 0; o >>= 1) {
        s0 += __shfl_xor_sync(0xffffffffu, s0, o);
        s1 += __shfl_xor_sync(0xffffffffu, s1, o);
        s2 += __shfl_xor_sync(0xffffffffu, s2, o);
        s3 += __shfl_xor_sync(0xffffffffu, s3, o);
    }
    __shared__ float red[4][4];
    __shared__ float sn[2][128];
    if ((c & 31) == 0) {
        int w = c >> 5;
        red[w][0] = s0; red[w][1] = s1; red[w][2] = s2; red[w][3] = s3;
    }
    __syncthreads();
    float qs  = red[0][0] + red[1][0] + red[2][0] + red[3][0];
    float qss = red[0][1] + red[1][1] + red[2][1] + red[3][1];
    float ks  = red[0][2] + red[1][2] + red[2][2] + red[3][2];
    float kss = red[0][3] + red[1][3] + red[2][3] + red[3][3];

    const float inv128 = 1.f / 128.f;
    float qmu = qs * inv128, kmu = ks * inv128;
    float qvar = qss * inv128 - qmu * qmu;
    float kvar = kss * inv128 - kmu * kmu;
    float qr = rsqrtf(qvar + 1e-6f);
    float kr = rsqrtf(kvar + 1e-6f);
    float qn = (qv - qmu) * qr * qw[c];
    float kn = (kv - kmu) * kr * kw[c];
    sn[0][c] = qn;
    sn[1][c] = kn;
    __syncthreads();

    int i = c >> 1;
    float inv = __powf(10000.f, -(float)(2 * i) * (1.f / 128.f));
    float fr = (float)t * inv;
    float sf, cf;
    sincosf(fr, &sf, &cf);
    float qp = sn[0][c ^ 1], kp = sn[1][c ^ 1];
    float qo = (c & 1) ? fmaf(qn, cf, qp * sf) : fmaf(qn, cf, -qp * sf);
    float ko = (c & 1) ? fmaf(kn, cf, kp * sf) : fmaf(kn, cf, -kp * sf);

    const float scale = 0.08838834764831845f;  // 1/sqrt(128)
    size_t oidx = ((size_t)h * TT + t) * CC + c;
    Qo[oidx] = tf32_rn(qo * scale);
    Ko[oidx] = tf32_rn(ko);
    Vo[oidx] = tf32_rn(vv);
}

// ---------------------------------------------------------------------------
// Causal flash attention with mma.sync tf32 — unchanged from R8 (known-good)
// ---------------------------------------------------------------------------
#define AQ_PAD 132
#define AK_PAD 132
#define AV_PAD 136
#define AS_PAD 68
#define ATT_SMEM ((128 * AQ_PAD + 64 * AK_PAD + 64 * AV_PAD + 128 * AS_PAD) * 4)

__global__ __launch_bounds__(256) void flash_attn_mma(
    const float* __restrict__ Qg, const float* __restrict__ Kg,
    const float* __restrict__ Vg, float* __restrict__ Og)
{
    extern __shared__ float sm[];
    float* Qs = sm;                       // [128][132]
    float* Ks = Qs + 128 * AQ_PAD;        // [64][132]
    float* Vs = Ks + 64 * AK_PAD;         // [64][136]
    float* Ss = Vs + 64 * AV_PAD;         // [128][68]
    __shared__ float m_s[128], l_s[128], al_s[128];

    const int tid = threadIdx.x;
    const int wid = tid >> 5, lane = tid & 31;
    const int warp_m = wid & 3, warp_n = wid >> 2;
    const int gr = lane >> 2, gc = lane & 3;
    const int qb = blockIdx.x, h = blockIdx.y;
    const int qm0 = qb * 128;
    const float* Qh = Qg + (size_t)h * TT * CC;
    const float* Kh = Kg + (size_t)h * TT * CC;
    const float* Vh = Vg + (size_t)h * TT * CC;

    // Load Q tile (tf32-rounded, pre-scaled already)
#pragma unroll
    for (int i = 0; i < 16; i++) {
        int q = tid + i * 256;
        int r = q >> 5, c4 = (q & 31) << 2;
        *(float4*)(Qs + r * AQ_PAD + c4) =
            *(const float4*)(Qh + (size_t)(qm0 + r) * CC + c4);
    }
    if (tid < 128) { m_s[tid] = -1e30f; l_s[tid] = 0.f; }

    float acc_o[2][8][4];
#pragma unroll
    for (int mt = 0; mt < 2; mt++)
#pragma unroll
        for (int nt = 0; nt < 8; nt++)
#pragma unroll
            for (int c = 0; c < 4; c++) acc_o[mt][nt][c] = 0.f;

    const int nkb = 2 * qb + 2;
    for (int kb = 0; kb < nkb; kb++) {
        __syncthreads();   // prev PV done with Vs/Ss; Q ready on iter 0
#pragma unroll
        for (int i = 0; i < 8; i++) {
            int q = tid + i * 256;
            int r = q >> 5, c4 = (q & 31) << 2;
            *(float4*)(Ks + r * AK_PAD + c4) =
                *(const float4*)(Kh + (size_t)(kb * 64 + r) * CC + c4);
            *(float4*)(Vs + r * AV_PAD + c4) =
                *(const float4*)(Vh + (size_t)(kb * 64 + r) * CC + c4);
        }
        __syncthreads();

        // ---- S[128][64] = Q @ K^T ----
        float accs[2][4][4];
#pragma unroll
        for (int mt = 0; mt < 2; mt++)
#pragma unroll
            for (int nt = 0; nt < 4; nt++)
#pragma unroll
                for (int c = 0; c < 4; c++) accs[mt][nt][c] = 0.f;
#pragma unroll
        for (int ks = 0; ks < 16; ks++) {
            const int k0 = ks * 8;
            uint32_t af[2][4];
#pragma unroll
            for (int mt = 0; mt < 2; mt++) {
                int r = warp_m * 32 + mt * 16 + gr;
                int o0 = r * AQ_PAD + k0 + gc, o1 = (r + 8) * AQ_PAD + k0 + gc;
                af[mt][0] = __float_as_uint(Qs[o0]);
                af[mt][1] = __float_as_uint(Qs[o1]);
                af[mt][2] = __float_as_uint(Qs[o0 + 4]);
                af[mt][3] = __float_as_uint(Qs[o1 + 4]);
            }
#pragma unroll
            for (int nt = 0; nt < 4; nt++) {
                int n = warp_n * 32 + nt * 8 + gr;
                uint32_t b0 = __float_as_uint(Ks[n * AK_PAD + k0 + gc]);
                uint32_t b1 = __float_as_uint(Ks[n * AK_PAD + k0 + 4 + gc]);
#pragma unroll
                for (int mt = 0; mt < 2; mt++)
                    mma_tf32(accs[mt][nt][0], accs[mt][nt][1],
                             accs[mt][nt][2], accs[mt][nt][3],
                             af[mt][0], af[mt][1], af[mt][2], af[mt][3],
                             b0, b1);
            }
        }

        // ---- mask (only blocks crossing the diagonal) + store S ----
        const bool need_mask = (kb >= 2 * qb);
#pragma unroll
        for (int mt = 0; mt < 2; mt++) {
            int rl = warp_m * 32 + mt * 16 + gr;
#pragma unroll
            for (int nt = 0; nt < 4; nt++) {
                int cl = warp_n * 32 + nt * 8 + 2 * gc;
                float v0 = accs[mt][nt][0], v1 = accs[mt][nt][1];
                float v2 = accs[mt][nt][2], v3 = accs[mt][nt][3];
                if (need_mask) {
                    int qg0 = qm0 + rl, qg1 = qg0 + 8;
                    int sg0 = kb * 64 + cl, sg1 = sg0 + 1;
                    if (sg0 > qg0) v0 = -1e30f;
                    if (sg1 > qg0) v1 = -1e30f;
                    if (sg0 > qg1) v2 = -1e30f;
                    if (sg1 > qg1) v3 = -1e30f;
                }
                *(float2*)(Ss + rl * AS_PAD + cl) = make_float2(v0, v1);
                *(float2*)(Ss + (rl + 8) * AS_PAD + cl) = make_float2(v2, v3);
            }
        }
        __syncthreads();

        // ---- online softmax (2 threads per row) ----
        {
            int r = tid >> 1, half = tid & 1;
            float* row = Ss + r * AS_PAD + half * 32;
            float mx = -1e30f;
#pragma unroll
            for (int j = 0; j < 32; j++) mx = fmaxf(mx, row[j]);
            mx = fmaxf(mx, __shfl_xor_sync(0xffffffffu, mx, 1));
            float mold = m_s[r];
            float mnew = fmaxf(mold, mx);
            float ps = 0.f;
#pragma unroll
            for (int j = 0; j < 32; j++) {
                float p = __expf(row[j] - mnew);
                ps += p;
                row[j] = tf32_rn(p);
            }
            ps += __shfl_xor_sync(0xffffffffu, ps, 1);
            if (half == 0) {
                float al = __expf(mold - mnew);
                al_s[r] = al;
                m_s[r] = mnew;
                l_s[r] = l_s[r] * al + ps;
            }
        }
        __syncthreads();

        // ---- rescale O, then O += P @ V ----
#pragma unroll
        for (int mt = 0; mt < 2; mt++) {
            int rl = warp_m * 32 + mt * 16 + gr;
            float a0 = al_s[rl], a1 = al_s[rl + 8];
#pragma unroll
            for (int nt = 0; nt < 8; nt++) {
                acc_o[mt][nt][0] *= a0; acc_o[mt][nt][1] *= a0;
                acc_o[mt][nt][2] *= a1; acc_o[mt][nt][3] *= a1;
            }
        }
#pragma unroll
        for (int ks = 0; ks < 8; ks++) {
            const int k0 = ks * 8;
            uint32_t af[2][4];
#pragma unroll
            for (int mt = 0; mt < 2; mt++) {
                int r = warp_m * 32 + mt * 16 + gr;
                int o0 = r * AS_PAD + k0 + gc, o1 = (r + 8) * AS_PAD + k0 + gc;
                af[mt][0] = __float_as_uint(Ss[o0]);
                af[mt][1] = __float_as_uint(Ss[o1]);
                af[mt][2] = __float_as_uint(Ss[o0 + 4]);
                af[mt][3] = __float_as_uint(Ss[o1 + 4]);
            }
#pragma unroll
            for (int nt = 0; nt < 8; nt++) {
                int n = warp_n * 64 + nt * 8 + gr;
                uint32_t b0 = __float_as_uint(Vs[(k0 + gc) * AV_PAD + n]);
                uint32_t b1 = __float_as_uint(Vs[(k0 + 4 + gc) * AV_PAD + n]);
#pragma unroll
                for (int mt = 0; mt < 2; mt++)
                    mma_tf32(acc_o[mt][nt][0], acc_o[mt][nt][1],
                             acc_o[mt][nt][2], acc_o[mt][nt][3],
                             af[mt][0], af[mt][1], af[mt][2], af[mt][3],
                             b0, b1);
            }
        }
    }

    // ---- normalize + store to [T][D] ----
#pragma unroll
    for (int mt = 0; mt < 2; mt++) {
        int rl = warp_m * 32 + mt * 16 + gr;
        float inv0 = 1.f / l_s[rl], inv1 = 1.f / l_s[rl + 8];
#pragma unroll
        for (int nt = 0; nt < 8; nt++) {
            int c = warp_n * 64 + nt * 8 + 2 * gc;
            float* r0 = Og + (size_t)(qm0 + rl) * DD + h * CC + c;
            float* r1 = Og + (size_t)(qm0 + rl + 8) * DD + h * CC + c;
            *(float2*)r0 = make_float2(acc_o[mt][nt][0] * inv0,
                                       acc_o[mt][nt][1] * inv0);
            *(float2*)r1 = make_float2(acc_o[mt][nt][2] * inv1,
                                       acc_o[mt][nt][3] * inv1);
        }
    }
}

// ---------------------------------------------------------------------------
// Launch
// ---------------------------------------------------------------------------
extern "C" void kernel_launch(void* const* d_in, const int* in_sizes, int n_in,
                              void* d_out, int out_size)
{
    const float* x  = (const float*)d_in[0];
    const float* Wa = (const float*)d_in[1];
    const float* ba = (const float*)d_in[2];
    const float* Wp = (const float*)d_in[3];
    const float* bp = (const float*)d_in[4];
    const float* qw = (const float*)d_in[5];
    const float* kw = (const float*)d_in[6];
    float* out = (float*)d_out;

    float *qkv, *q, *k, *v, *att;
    cudaGetSymbolAddress((void**)&qkv, g_qkv);
    cudaGetSymbolAddress((void**)&q,   g_q);
    cudaGetSymbolAddress((void**)&k,   g_k);
    cudaGetSymbolAddress((void**)&v,   g_v);
    cudaGetSymbolAddress((void**)&att, g_att);

    cudaFuncSetAttribute(gemm_tf32p, cudaFuncAttributeMaxDynamicSharedMemorySize, GEMM_SMEM);
    cudaFuncSetAttribute(flash_attn_mma, cudaFuncAttributeMaxDynamicSharedMemorySize, ATT_SMEM);

    // 1) qkv = x @ W_attn^T + b_attn  (plain tf32 mma.sync)
    gemm_tf32p<<<dim3(D3 / BN, TT / BM), 256, GEMM_SMEM>>>(
        x, Wa, ba, qkv, TT, D3, DD);

    // 2) LN + RoPE + split (tf32-rounded outputs, q pre-scaled)
    ln_rope_split<<<dim3(TT, HH), 128>>>(qkv, qw, kw, q, k, v);

    // 3) causal flash attention (tf32 mma.sync)
    flash_attn_mma<<<dim3(TT / 128, HH), 256, ATT_SMEM>>>(q, k, v, att);

    // 4) out = att @ W_proj^T + b_proj  (plain tf32 mma.sync)
    gemm_tf32p<<<dim3(DD / BN, TT / BM), 256, GEMM_SMEM>>>(
        att, Wp, bp, out, TT, DD, DD);
}